// round 1
// baseline (speedup 1.0000x reference)
#include <cuda_runtime.h>
#include <math.h>
#include <stdint.h>

// ---------------- problem constants ----------------
#define NB    8
#define HI_   56
#define WI_   56
#define HO_   28
#define WO_   28
#define NIN   3136            // 56*56
#define NOUT  784             // 28*28
#define DIN   96
#define DOUT  192
#define HID   384
#define RTOT  (NB*NIN)        // 25088
#define ROUT  (NB*NOUT)       // 6272
#define KCONV 864             // 9*96

// output layout in d_out (floats): x_out | a_ups | a_down
#define OFF_X     0
#define OFF_AUPS  ((size_t)ROUT*DOUT)                       // 1204224
#define OFF_ADOWN (OFF_AUPS + (size_t)NB*NIN*NOUT)          // 20873216
#define A_TOTAL   ((size_t)2*NB*NIN*NOUT)                   // 39337984

// ---------------- scratch (device globals; no allocs) ----------------
__device__ float g_xn  [RTOT*DIN];
__device__ float g_k   [RTOT*DIN];
__device__ float g_v   [RTOT*DOUT];
__device__ float g_xout[ROUT*DOUT];
__device__ float g_lnq [ROUT*DOUT];
__device__ float g_q   [ROUT*DIN];
__device__ float g_p   [RTOT*9];
__device__ float g_cs  [ROUT];
__device__ float g_h   [ROUT*HID];
__device__ float g_h2  [ROUT*DOUT];
__device__ float g_ai  [ROUT*KCONV];
__device__ float g_wt  [DOUT*KCONV];

// ---------------- helpers ----------------
__device__ __forceinline__ int drmax(int p, int o) {
    // max d in {-1,0,1} with clip(p+d,0,27)==o  (last-writer (torch qidx) rule)
    int best = -2;
#pragma unroll
    for (int d = -1; d <= 1; ++d) {
        int c = p + d; c = c < 0 ? 0 : (c > 27 ? 27 : c);
        if (c == o) best = d;
    }
    return best;
}

// ---------------- zero / copy ----------------
__global__ void zero_kernel(float4* p, long long n4) {
    long long i = (long long)blockIdx.x * blockDim.x + threadIdx.x;
    long long stride = (long long)gridDim.x * blockDim.x;
    float4 z = make_float4(0.f, 0.f, 0.f, 0.f);
    for (; i < n4; i += stride) p[i] = z;
}
__global__ void copy_xout_kernel(float* dst) {
    int i = blockIdx.x * blockDim.x + threadIdx.x;
    if (i < ROUT*DOUT) dst[i] = g_xout[i];
}

// ---------------- layernorm (block per row) ----------------
template<int D, bool RES>
__global__ void __launch_bounds__(D) ln_kernel(const float* __restrict__ in,
                                               const float* __restrict__ gg,
                                               const float* __restrict__ bb,
                                               float* __restrict__ out) {
    __shared__ float r1[8], r2[8];
    int row = blockIdx.x;
    int t = threadIdx.x;
    float v = in[(size_t)row * D + t];
    float s1 = v, s2 = v * v;
#pragma unroll
    for (int o = 16; o; o >>= 1) {
        s1 += __shfl_xor_sync(0xffffffffu, s1, o);
        s2 += __shfl_xor_sync(0xffffffffu, s2, o);
    }
    int wid = t >> 5, lane = t & 31;
    if (lane == 0) { r1[wid] = s1; r2[wid] = s2; }
    __syncthreads();
    if (t == 0) {
        float a = 0.f, c = 0.f;
        const int NW = D / 32;
        for (int w = 0; w < NW; ++w) { a += r1[w]; c += r2[w]; }
        r1[0] = a; r2[0] = c;
    }
    __syncthreads();
    float mu  = r1[0] / (float)D;
    float var = r2[0] / (float)D - mu * mu;
    float y = (v - mu) * rsqrtf(var + 1e-5f) * gg[t] + bb[t];
    if (RES) out[(size_t)row * D + t] += y;
    else     out[(size_t)row * D + t]  = y;
}

// ---------------- SGEMM: C[M,N] = A[M,K] * B[N,K]^T (+bias)(+gelu) ----------------
// BM=128, BN=64, BK=16, 256 threads, 8x4 per thread. M%128==0, K%16==0, N%4==0.
template<int EPI> // 0: none, 1: +bias, 2: +bias then exact gelu
__global__ void __launch_bounds__(256) gemm_kernel(const float* __restrict__ A,
                                                   const float* __restrict__ Bw,
                                                   const float* __restrict__ bias,
                                                   float* __restrict__ C,
                                                   int M, int N, int K) {
    const int BM = 128, BN = 64, BK = 16;
    __shared__ float As[BK][BM];
    __shared__ float Bs[BK][BN];
    int tid = threadIdx.x;
    int bn0 = blockIdx.x * BN;
    int bm0 = blockIdx.y * BM;
    int tx = tid & 15, ty = tid >> 4;
    float acc[8][4] = {};
    for (int k0 = 0; k0 < K; k0 += BK) {
#pragma unroll
        for (int l = 0; l < 2; ++l) {
            int f = tid + l * 256;
            int row = f >> 2;
            int kq = (f & 3) << 2;
            float4 va = *(const float4*)&A[(size_t)(bm0 + row) * K + k0 + kq];
            As[kq + 0][row] = va.x; As[kq + 1][row] = va.y;
            As[kq + 2][row] = va.z; As[kq + 3][row] = va.w;
        }
        {
            int row = tid >> 2;
            int kq = (tid & 3) << 2;
            float4 vb = make_float4(0.f, 0.f, 0.f, 0.f);
            if (bn0 + row < N)
                vb = *(const float4*)&Bw[(size_t)(bn0 + row) * K + k0 + kq];
            Bs[kq + 0][row] = vb.x; Bs[kq + 1][row] = vb.y;
            Bs[kq + 2][row] = vb.z; Bs[kq + 3][row] = vb.w;
        }
        __syncthreads();
#pragma unroll
        for (int kk = 0; kk < BK; ++kk) {
            float a[8], b[4];
#pragma unroll
            for (int i = 0; i < 8; ++i) a[i] = As[kk][ty * 8 + i];
#pragma unroll
            for (int j = 0; j < 4; ++j) b[j] = Bs[kk][tx * 4 + j];
#pragma unroll
            for (int i = 0; i < 8; ++i)
#pragma unroll
                for (int j = 0; j < 4; ++j)
                    acc[i][j] += a[i] * b[j];
        }
        __syncthreads();
    }
    int c0 = bn0 + tx * 4;
    if (c0 < N) {
#pragma unroll
        for (int i = 0; i < 8; ++i) {
            int r = bm0 + ty * 8 + i;
            float o4[4];
#pragma unroll
            for (int j = 0; j < 4; ++j) {
                float vv = acc[i][j];
                if (EPI >= 1) vv += bias[c0 + j];
                if (EPI == 2) vv = 0.5f * vv * (1.0f + erff(vv * 0.70710678118654752f));
                o4[j] = vv;
            }
            *(float4*)&C[(size_t)r * N + c0] = *(float4*)o4;
        }
    }
}

// ---------------- conv setup ----------------
__global__ void wt_reorder_kernel(const float* __restrict__ conv_w) {
    int idx = blockIdx.x * blockDim.x + threadIdx.x;
    if (idx >= DOUT * KCONV) return;
    int o = idx / KCONV, c = idx % KCONV;
    int tap = c / DIN, i = c % DIN;
    g_wt[idx] = conv_w[((size_t)o * DIN + i) * 9 + tap];
}
__global__ void im2col_kernel(const float* __restrict__ x) {
    int idx = blockIdx.x * blockDim.x + threadIdx.x;
    if (idx >= ROUT * KCONV) return;
    int r = idx / KCONV, c = idx % KCONV;
    int b = r / NOUT, m = r % NOUT;
    int orr = m / WO_, occ = m % WO_;
    int tap = c / DIN, i = c % DIN;
    int ir = 2 * orr + tap / 3 - 1;
    int ic = 2 * occ + tap % 3 - 1;
    float v = 0.f;
    if (ir >= 0 && ir < HI_ && ic >= 0 && ic < WI_)
        v = x[((size_t)b * NIN + ir * WI_ + ic) * DIN + i];
    g_ai[idx] = v;
}

// ---------------- sparse attention: per-token softmax over <=9 slots ----------------
__global__ void __launch_bounds__(256) attn_kernel(const float* __restrict__ rpb,
                                                   const float* __restrict__ taup) {
    int gw = blockIdx.x * 8 + (threadIdx.x >> 5);
    int lane = threadIdx.x & 31;
    int b = gw / NIN, n = gw % NIN;
    int ir = n / WI_, ic = n % WI_;
    int pr = ir >> 1, pc = ic >> 1;
    const float* kr = &g_k[((size_t)b * NIN + n) * DIN];
    float kv0 = kr[lane], kv1 = kr[lane + 32], kv2 = kr[lane + 64];
    float scale = expf(*taup);
    float l[9];
#pragma unroll
    for (int k = 0; k < 9; ++k) {
        int dr = k / 3 - 1, dc = k % 3 - 1;
        int o_r = min(max(pr + dr, 0), HO_ - 1);
        int o_c = min(max(pc + dc, 0), WO_ - 1);
        bool rep = (dr == drmax(pr, o_r)) && (dc == drmax(pc, o_c));
        float s = -1e30f;
        if (rep) {
            int m = o_r * WO_ + o_c;
            const float* qr = &g_q[((size_t)b * NOUT + m) * DIN];
            float d0 = kv0 * qr[lane] + kv1 * qr[lane + 32] + kv2 * qr[lane + 64];
#pragma unroll
            for (int o = 16; o; o >>= 1) d0 += __shfl_xor_sync(0xffffffffu, d0, o);
            s = d0 * scale + rpb[k];
        }
        l[k] = s;
    }
    float mx = l[0];
#pragma unroll
    for (int k = 1; k < 9; ++k) mx = fmaxf(mx, l[k]);
    float e[9], sum = 0.f;
#pragma unroll
    for (int k = 0; k < 9; ++k) {
        e[k] = (l[k] > -1e29f) ? expf(l[k] - mx) : 0.f;
        sum += e[k];
    }
    float inv = 1.f / sum;
    if (lane == 0) {
        float* pp = &g_p[((size_t)b * NIN + n) * 9];
#pragma unroll
        for (int k = 0; k < 9; ++k) pp[k] = e[k] * inv;
    }
}

// ---------------- gather updates (+col sums) + LN + residual ----------------
__global__ void __launch_bounds__(DOUT) updates_kernel(const float* __restrict__ g_attn,
                                                       const float* __restrict__ b_attn) {
    __shared__ float sp[36];
    __shared__ int   sn[36];
    __shared__ float r1[8], r2[8], s_inv;
    int bm = blockIdx.x;
    int b = bm / NOUT, m = bm % NOUT;
    int orr = m / WO_, occ = m % WO_;
    int ir0 = max(2 * orr - 2, 0), ir1 = min(2 * orr + 3, HI_ - 1);
    int ic0 = max(2 * occ - 2, 0), ic1 = min(2 * occ + 3, WI_ - 1);
    int nr = ir1 - ir0 + 1, nc = ic1 - ic0 + 1;
    int cnt = nr * nc;
    int t = threadIdx.x;
    if (t < cnt) {
        int irr = ir0 + t / nc, icc = ic0 + t % nc;
        int n = irr * WI_ + icc;
        int kmax = (drmax(irr >> 1, orr) + 1) * 3 + (drmax(icc >> 1, occ) + 1);
        sp[t] = g_p[((size_t)b * NIN + n) * 9 + kmax];
        sn[t] = n;
    }
    __syncthreads();
    // deterministic column sum (replaces atomics)
    if (t == 0) {
        float cs = 0.f;
        for (int j = 0; j < cnt; ++j) cs += sp[j];
        g_cs[bm] = cs;
        s_inv = 1.f / (cs + 1e-8f);
    }
    __syncthreads();
    float acc = 0.f;
    for (int j = 0; j < cnt; ++j)
        acc += sp[j] * g_v[((size_t)b * NIN + sn[j]) * DOUT + t];
    float u = acc * s_inv;
    // LN over 192
    float s1 = u, s2 = u * u;
#pragma unroll
    for (int o = 16; o; o >>= 1) {
        s1 += __shfl_xor_sync(0xffffffffu, s1, o);
        s2 += __shfl_xor_sync(0xffffffffu, s2, o);
    }
    int wid = t >> 5, lane = t & 31;
    if (lane == 0) { r1[wid] = s1; r2[wid] = s2; }
    __syncthreads();
    if (t == 0) {
        float a = 0.f, c = 0.f;
        for (int w = 0; w < 6; ++w) { a += r1[w]; c += r2[w]; }
        r1[0] = a; r2[0] = c;
    }
    __syncthreads();
    float mu  = r1[0] / (float)DOUT;
    float var = r2[0] / (float)DOUT - mu * mu;
    float y = (u - mu) * rsqrtf(var + 1e-5f) * g_attn[t] + b_attn[t];
    g_xout[(size_t)bm * DOUT + t] += y;
}

// ---------------- final sparse scatter of a_ups / a_down ----------------
__global__ void scatter_kernel(float* __restrict__ aups, float* __restrict__ adown) {
    int gw = blockIdx.x * blockDim.x + threadIdx.x;
    if (gw >= RTOT) return;
    int b = gw / NIN, n = gw % NIN;
    int ir = n / WI_, ic = n % WI_;
    int pr = ir >> 1, pc = ic >> 1;
    const float* pp = &g_p[(size_t)gw * 9];
    size_t rowbase = (size_t)gw * NOUT;
#pragma unroll
    for (int k = 0; k < 9; ++k) {
        int dr = k / 3 - 1, dc = k % 3 - 1;
        int o_r = min(max(pr + dr, 0), HO_ - 1);
        int o_c = min(max(pc + dc, 0), WO_ - 1);
        if (dr == drmax(pr, o_r) && dc == drmax(pc, o_c)) {
            int m = o_r * WO_ + o_c;
            float p = pp[k];
            aups[rowbase + m]  = p;
            adown[rowbase + m] = p / (g_cs[b * NOUT + m] + 1e-8f);
        }
    }
}

// ---------------- host launch ----------------
extern "C" void kernel_launch(void* const* d_in, const int* in_sizes, int n_in,
                              void* d_out, int out_size) {
    const float* x      = (const float*)d_in[0];
    const float* conv_w = (const float*)d_in[1];
    const float* q_w    = (const float*)d_in[2];
    const float* k_w    = (const float*)d_in[3];
    const float* v_w    = (const float*)d_in[4];
    const float* w1     = (const float*)d_in[5];
    const float* b1     = (const float*)d_in[6];
    const float* w2     = (const float*)d_in[7];
    const float* b2     = (const float*)d_in[8];
    const float* ln_in_g  = (const float*)d_in[9];
    const float* ln_in_b  = (const float*)d_in[10];
    const float* ln_out_g = (const float*)d_in[11];
    const float* ln_out_b = (const float*)d_in[12];
    const float* ln_at_g  = (const float*)d_in[13];
    const float* ln_at_b  = (const float*)d_in[14];
    const float* ln_ml_g  = (const float*)d_in[15];
    const float* ln_ml_b  = (const float*)d_in[16];
    const float* tau    = (const float*)d_in[17];
    const float* rpb    = (const float*)d_in[18];
    float* out = (float*)d_out;

    float *pxn, *pk, *pv, *pxout, *plnq, *pq, *ph, *ph2, *pai, *pwt;
    cudaGetSymbolAddress((void**)&pxn,  g_xn);
    cudaGetSymbolAddress((void**)&pk,   g_k);
    cudaGetSymbolAddress((void**)&pv,   g_v);
    cudaGetSymbolAddress((void**)&pxout,g_xout);
    cudaGetSymbolAddress((void**)&plnq, g_lnq);
    cudaGetSymbolAddress((void**)&pq,   g_q);
    cudaGetSymbolAddress((void**)&ph,   g_h);
    cudaGetSymbolAddress((void**)&ph2,  g_h2);
    cudaGetSymbolAddress((void**)&pai,  g_ai);
    cudaGetSymbolAddress((void**)&pwt,  g_wt);

    // zero the dense a_ups / a_down output regions (scatter fills sparse support)
    zero_kernel<<<4096, 256>>>((float4*)(out + OFF_AUPS), (long long)(A_TOTAL / 4));

    // xn = LN(x)
    ln_kernel<DIN, false><<<RTOT, DIN>>>(x, ln_in_g, ln_in_b, pxn);
    // k, v projections
    gemm_kernel<0><<<dim3(2, RTOT / 128), 256>>>(pxn, k_w, nullptr, pk, RTOT, DIN, DIN);
    gemm_kernel<0><<<dim3(3, RTOT / 128), 256>>>(pxn, v_w, nullptr, pv, RTOT, DOUT, DIN);

    // conv seed via im2col GEMM, then LN -> x_out
    wt_reorder_kernel<<<(DOUT * KCONV + 255) / 256, 256>>>(conv_w);
    im2col_kernel<<<(ROUT * KCONV + 255) / 256, 256>>>(x);
    gemm_kernel<0><<<dim3(3, ROUT / 128), 256>>>(pai, pwt, nullptr, ph2, ROUT, DOUT, KCONV);
    ln_kernel<DOUT, false><<<ROUT, DOUT>>>(ph2, ln_out_g, ln_out_b, pxout);

    for (int it = 0; it < 3; ++it) {
        // q = LN(x_out) @ q_w^T
        ln_kernel<DOUT, false><<<ROUT, DOUT>>>(pxout, ln_out_g, ln_out_b, plnq);
        gemm_kernel<0><<<dim3(2, ROUT / 128), 256>>>(plnq, q_w, nullptr, pq, ROUT, DIN, DOUT);
        // sparse softmax per input token
        attn_kernel<<<RTOT / 8, 256>>>(rpb, tau);
        // gather updates + col renorm + LN + residual
        updates_kernel<<<ROUT, DOUT>>>(ln_at_g, ln_at_b);
        // MLP
        gemm_kernel<2><<<dim3(6, ROUT / 128), 256>>>(pxout, w1, b1, ph, ROUT, HID, DOUT);
        gemm_kernel<1><<<dim3(3, ROUT / 128), 256>>>(ph, w2, b2, ph2, ROUT, DOUT, HID);
        ln_kernel<DOUT, true><<<ROUT, DOUT>>>(ph2, ln_ml_g, ln_ml_b, pxout);
    }

    // outputs
    scatter_kernel<<<(RTOT + 127) / 128, 128>>>(out + OFF_AUPS, out + OFF_ADOWN);
    copy_xout_kernel<<<(ROUT * DOUT + 255) / 256, 256>>>(out + OFF_X);
}

// round 3
// speedup vs baseline: 1.4199x; 1.4199x over previous
#include <cuda_runtime.h>
#include <math.h>
#include <stdint.h>

// ---------------- problem constants ----------------
#define NB    8
#define HI_   56
#define WI_   56
#define HO_   28
#define WO_   28
#define NIN   3136
#define NOUT  784
#define DIN   96
#define DOUT  192
#define HID   384
#define RTOT  (NB*NIN)        // 25088
#define ROUT  (NB*NOUT)       // 6272
#define KCONV 864

// output layout in d_out (floats): x_out | a_ups | a_down
#define OFF_X     0
#define OFF_AUPS  ((size_t)ROUT*DOUT)
#define OFF_ADOWN (OFF_AUPS + (size_t)NB*NIN*NOUT)

// ---------------- scratch ----------------
__device__ float g_xn  [RTOT*DIN];
__device__ float g_k   [RTOT*DIN];
__device__ float g_v   [RTOT*DOUT];
__device__ float g_xout[ROUT*DOUT];
__device__ float g_lnq [ROUT*DOUT];
__device__ float g_q   [ROUT*DIN];
__device__ float g_p   [RTOT*9];
__device__ float g_cs  [ROUT];
__device__ float g_h   [ROUT*HID];
__device__ float g_h2  [ROUT*DOUT];
__device__ float g_ai  [ROUT*KCONV];
__device__ float g_wt  [DOUT*KCONV];

// ---------------- helpers ----------------
__device__ __forceinline__ uint32_t f2tf(float f) {
    uint32_t r;
    asm("cvt.rna.tf32.f32 %0, %1;" : "=r"(r) : "f"(f));
    return r;
}
__device__ __forceinline__ void mma_tf32(float* c, const uint32_t* a, const uint32_t* b) {
    asm volatile(
        "mma.sync.aligned.m16n8k8.row.col.f32.tf32.tf32.f32 "
        "{%0,%1,%2,%3}, {%4,%5,%6,%7}, {%8,%9}, {%0,%1,%2,%3};"
        : "+f"(c[0]), "+f"(c[1]), "+f"(c[2]), "+f"(c[3])
        : "r"(a[0]), "r"(a[1]), "r"(a[2]), "r"(a[3]), "r"(b[0]), "r"(b[1]));
}
__device__ __forceinline__ int drmax(int p, int o) {
    int best = -2;
#pragma unroll
    for (int d = -1; d <= 1; ++d) {
        int c = p + d; c = c < 0 ? 0 : (c > 27 ? 27 : c);
        if (c == o) best = d;
    }
    return best;
}

// ---------------- tensor-core tf32 GEMM: C[M,N] = A[M,K] * B[N,K]^T ----------------
// BM=128, BN=64, BK=32, 256 threads (8 warps, 4x2), warp tile 32x32.
// Requires M%128==0, K%32==0. N handled with guards (N%8==0 assumed).
// EPI: 0 none, 1 +bias, 2 +bias then exact gelu.
#define BKP 36   // padded k-stride in words
template<int EPI>
__global__ void __launch_bounds__(256) gemm_mma(const float* __restrict__ A,
                                                const float* __restrict__ Bw,
                                                const float* __restrict__ bias,
                                                float* __restrict__ C,
                                                int M, int N, int K) {
    __shared__ uint32_t As[128 * BKP];
    __shared__ uint32_t Bs[64 * BKP];

    const int tid = threadIdx.x;
    const int wid = tid >> 5;
    const int lane = tid & 31;
    const int gid = lane >> 2, tig = lane & 3;
    const int wm = wid & 3, wn = wid >> 2;          // 4x2 warp grid
    const int m_base = wm * 32, n_base = wn * 32;

    const int bm0 = blockIdx.y * 128;
    const int bn0 = blockIdx.x * 64;

    float acc[2][4][4];
#pragma unroll
    for (int i = 0; i < 2; ++i)
#pragma unroll
        for (int j = 0; j < 4; ++j)
#pragma unroll
            for (int e = 0; e < 4; ++e) acc[i][j][e] = 0.f;

    for (int k0 = 0; k0 < K; k0 += 32) {
        // ---- load A tile: 128x32 (1024 float4, 4 per thread) ----
#pragma unroll
        for (int l = 0; l < 4; ++l) {
            int f = tid + l * 256;
            int row = f >> 3, ch = f & 7;
            const float4 v = *(const float4*)&A[(size_t)(bm0 + row) * K + k0 + ch * 4];
            uint32_t* d = &As[row * BKP + ch * 4];
            d[0] = f2tf(v.x); d[1] = f2tf(v.y); d[2] = f2tf(v.z); d[3] = f2tf(v.w);
        }
        // ---- load B tile: 64x32 (512 float4, 2 per thread), guard rows ----
#pragma unroll
        for (int l = 0; l < 2; ++l) {
            int f = tid + l * 256;
            int row = f >> 3, ch = f & 7;
            float4 v = make_float4(0.f, 0.f, 0.f, 0.f);
            if (bn0 + row < N)
                v = *(const float4*)&Bw[(size_t)(bn0 + row) * K + k0 + ch * 4];
            uint32_t* d = &Bs[row * BKP + ch * 4];
            d[0] = f2tf(v.x); d[1] = f2tf(v.y); d[2] = f2tf(v.z); d[3] = f2tf(v.w);
        }
        __syncthreads();
        // ---- compute: 4 k-substeps of 8 ----
#pragma unroll
        for (int ks = 0; ks < 4; ++ks) {
            const int kk = ks * 8;
            uint32_t af[2][4], bf[4][2];
#pragma unroll
            for (int mi = 0; mi < 2; ++mi) {
                const uint32_t* base = &As[(m_base + mi * 16 + gid) * BKP + kk + tig];
                af[mi][0] = base[0];
                af[mi][1] = base[8 * BKP];
                af[mi][2] = base[4];
                af[mi][3] = base[8 * BKP + 4];
            }
#pragma unroll
            for (int ni = 0; ni < 4; ++ni) {
                const uint32_t* base = &Bs[(n_base + ni * 8 + gid) * BKP + kk + tig];
                bf[ni][0] = base[0];
                bf[ni][1] = base[4];
            }
#pragma unroll
            for (int mi = 0; mi < 2; ++mi)
#pragma unroll
                for (int ni = 0; ni < 4; ++ni)
                    mma_tf32(acc[mi][ni], af[mi], bf[ni]);
        }
        __syncthreads();
    }

    // ---- epilogue ----
#pragma unroll
    for (int mi = 0; mi < 2; ++mi) {
#pragma unroll
        for (int ni = 0; ni < 4; ++ni) {
            int col = bn0 + n_base + ni * 8 + tig * 2;
            if (col >= N) continue;
            float bsum0 = 0.f, bsum1 = 0.f;
            if (EPI >= 1) { bsum0 = bias[col]; bsum1 = bias[col + 1]; }
#pragma unroll
            for (int half = 0; half < 2; ++half) {
                int r = bm0 + m_base + mi * 16 + gid + half * 8;
                float v0 = acc[mi][ni][half * 2 + 0] + bsum0;
                float v1 = acc[mi][ni][half * 2 + 1] + bsum1;
                if (EPI == 2) {
                    v0 = 0.5f * v0 * (1.0f + erff(v0 * 0.70710678118654752f));
                    v1 = 0.5f * v1 * (1.0f + erff(v1 * 0.70710678118654752f));
                }
                float2 o = make_float2(v0, v1);
                *(float2*)&C[(size_t)r * N + col] = o;
            }
        }
    }
}

// ---------------- misc small kernels ----------------
__global__ void copy_xout_kernel(float* dst) {
    int i = blockIdx.x * blockDim.x + threadIdx.x;
    if (i < ROUT*DOUT) dst[i] = g_xout[i];
}

template<int D, bool RES>
__global__ void __launch_bounds__(D) ln_kernel(const float* __restrict__ in,
                                               const float* __restrict__ gg,
                                               const float* __restrict__ bb,
                                               float* __restrict__ out) {
    __shared__ float r1[8], r2[8];
    int row = blockIdx.x;
    int t = threadIdx.x;
    float v = in[(size_t)row * D + t];
    float s1 = v, s2 = v * v;
#pragma unroll
    for (int o = 16; o; o >>= 1) {
        s1 += __shfl_xor_sync(0xffffffffu, s1, o);
        s2 += __shfl_xor_sync(0xffffffffu, s2, o);
    }
    int wid = t >> 5, lane = t & 31;
    if (lane == 0) { r1[wid] = s1; r2[wid] = s2; }
    __syncthreads();
    if (t == 0) {
        float a = 0.f, c = 0.f;
        const int NW = D / 32;
        for (int w = 0; w < NW; ++w) { a += r1[w]; c += r2[w]; }
        r1[0] = a; r2[0] = c;
    }
    __syncthreads();
    float mu  = r1[0] / (float)D;
    float var = r2[0] / (float)D - mu * mu;
    float y = (v - mu) * rsqrtf(var + 1e-5f) * gg[t] + bb[t];
    if (RES) out[(size_t)row * D + t] += y;
    else     out[(size_t)row * D + t]  = y;
}

__global__ void wt_reorder_kernel(const float* __restrict__ conv_w) {
    int idx = blockIdx.x * blockDim.x + threadIdx.x;
    if (idx >= DOUT * KCONV) return;
    int o = idx / KCONV, c = idx % KCONV;
    int tap = c / DIN, i = c % DIN;
    g_wt[idx] = conv_w[((size_t)o * DIN + i) * 9 + tap];
}
__global__ void im2col_kernel(const float* __restrict__ x) {
    int idx = blockIdx.x * blockDim.x + threadIdx.x;
    if (idx >= ROUT * KCONV) return;
    int r = idx / KCONV, c = idx % KCONV;
    int b = r / NOUT, m = r % NOUT;
    int orr = m / WO_, occ = m % WO_;
    int tap = c / DIN, i = c % DIN;
    int ir = 2 * orr + tap / 3 - 1;
    int ic = 2 * occ + tap % 3 - 1;
    float v = 0.f;
    if (ir >= 0 && ir < HI_ && ic >= 0 && ic < WI_)
        v = x[((size_t)b * NIN + ir * WI_ + ic) * DIN + i];
    g_ai[idx] = v;
}

// ---------------- sparse attention softmax ----------------
__global__ void __launch_bounds__(256) attn_kernel(const float* __restrict__ rpb,
                                                   const float* __restrict__ taup) {
    int gw = blockIdx.x * 8 + (threadIdx.x >> 5);
    int lane = threadIdx.x & 31;
    int b = gw / NIN, n = gw % NIN;
    int ir = n / WI_, ic = n % WI_;
    int pr = ir >> 1, pc = ic >> 1;
    const float* kr = &g_k[((size_t)b * NIN + n) * DIN];
    float kv0 = kr[lane], kv1 = kr[lane + 32], kv2 = kr[lane + 64];
    float scale = expf(*taup);
    float l[9];
#pragma unroll
    for (int k = 0; k < 9; ++k) {
        int dr = k / 3 - 1, dc = k % 3 - 1;
        int o_r = min(max(pr + dr, 0), HO_ - 1);
        int o_c = min(max(pc + dc, 0), WO_ - 1);
        bool rep = (dr == drmax(pr, o_r)) && (dc == drmax(pc, o_c));
        float s = -1e30f;
        if (rep) {
            int m = o_r * WO_ + o_c;
            const float* qr = &g_q[((size_t)b * NOUT + m) * DIN];
            float d0 = kv0 * qr[lane] + kv1 * qr[lane + 32] + kv2 * qr[lane + 64];
#pragma unroll
            for (int o = 16; o; o >>= 1) d0 += __shfl_xor_sync(0xffffffffu, d0, o);
            s = d0 * scale + rpb[k];
        }
        l[k] = s;
    }
    float mx = l[0];
#pragma unroll
    for (int k = 1; k < 9; ++k) mx = fmaxf(mx, l[k]);
    float e[9], sum = 0.f;
#pragma unroll
    for (int k = 0; k < 9; ++k) {
        e[k] = (l[k] > -1e29f) ? expf(l[k] - mx) : 0.f;
        sum += e[k];
    }
    float inv = 1.f / sum;
    if (lane == 0) {
        float* pp = &g_p[((size_t)b * NIN + n) * 9];
#pragma unroll
        for (int k = 0; k < 9; ++k) pp[k] = e[k] * inv;
    }
}

// ---------------- gather updates + col sums + LN + residual ----------------
__global__ void __launch_bounds__(DOUT) updates_kernel(const float* __restrict__ g_attn,
                                                       const float* __restrict__ b_attn) {
    __shared__ float sp[36];
    __shared__ int   sn[36];
    __shared__ float r1[8], r2[8], s_inv;
    int bm = blockIdx.x;
    int b = bm / NOUT, m = bm % NOUT;
    int orr = m / WO_, occ = m % WO_;
    int ir0 = max(2 * orr - 2, 0), ir1 = min(2 * orr + 3, HI_ - 1);
    int ic0 = max(2 * occ - 2, 0), ic1 = min(2 * occ + 3, WI_ - 1);
    int nr = ir1 - ir0 + 1, nc = ic1 - ic0 + 1;
    int cnt = nr * nc;
    int t = threadIdx.x;
    if (t < cnt) {
        int irr = ir0 + t / nc, icc = ic0 + t % nc;
        int n = irr * WI_ + icc;
        int kmax = (drmax(irr >> 1, orr) + 1) * 3 + (drmax(icc >> 1, occ) + 1);
        sp[t] = g_p[((size_t)b * NIN + n) * 9 + kmax];
        sn[t] = n;
    }
    __syncthreads();
    if (t == 0) {
        float cs = 0.f;
        for (int j = 0; j < cnt; ++j) cs += sp[j];
        g_cs[bm] = cs;
        s_inv = 1.f / (cs + 1e-8f);
    }
    __syncthreads();
    float acc = 0.f;
    for (int j = 0; j < cnt; ++j)
        acc += sp[j] * g_v[((size_t)b * NIN + sn[j]) * DOUT + t];
    float u = acc * s_inv;
    float s1 = u, s2 = u * u;
#pragma unroll
    for (int o = 16; o; o >>= 1) {
        s1 += __shfl_xor_sync(0xffffffffu, s1, o);
        s2 += __shfl_xor_sync(0xffffffffu, s2, o);
    }
    int wid = t >> 5, lane = t & 31;
    if (lane == 0) { r1[wid] = s1; r2[wid] = s2; }
    __syncthreads();
    if (t == 0) {
        float a = 0.f, c = 0.f;
        for (int w = 0; w < 6; ++w) { a += r1[w]; c += r2[w]; }
        r1[0] = a; r2[0] = c;
    }
    __syncthreads();
    float mu  = r1[0] / (float)DOUT;
    float var = r2[0] / (float)DOUT - mu * mu;
    float y = (u - mu) * rsqrtf(var + 1e-5f) * g_attn[t] + b_attn[t];
    g_xout[(size_t)bm * DOUT + t] += y;
}

// ---------------- dense row writer: a_ups & a_down in one pass ----------------
__global__ void __launch_bounds__(256) writeA_kernel(float* __restrict__ aups,
                                                     float* __restrict__ adown) {
    __shared__ float sp[9];
    int bn = blockIdx.x;
    int b = bn / NIN, n = bn % NIN;
    int pr = (n / WI_) >> 1, pc = (n % WI_) >> 1;
    int t = threadIdx.x;
    if (t < 9) sp[t] = g_p[(size_t)bn * 9 + t];
    __syncthreads();
    if (t >= 196) return;
    size_t rb = (size_t)bn * NOUT;
    float up[4], dn[4];
#pragma unroll
    for (int j = 0; j < 4; ++j) {
        int m = t * 4 + j;
        int o_r = m / WO_, o_c = m % WO_;
        int dr = drmax(pr, o_r), dc = drmax(pc, o_c);
        float u = 0.f, d = 0.f;
        if (dr >= -1 && dc >= -1) {
            u = sp[(dr + 1) * 3 + (dc + 1)];
            d = u / (g_cs[b * NOUT + m] + 1e-8f);
        }
        up[j] = u; dn[j] = d;
    }
    *(float4*)&aups[rb + t * 4]  = *(float4*)up;
    *(float4*)&adown[rb + t * 4] = *(float4*)dn;
}

// ---------------- host launch ----------------
extern "C" void kernel_launch(void* const* d_in, const int* in_sizes, int n_in,
                              void* d_out, int out_size) {
    const float* x      = (const float*)d_in[0];
    const float* conv_w = (const float*)d_in[1];
    const float* q_w    = (const float*)d_in[2];
    const float* k_w    = (const float*)d_in[3];
    const float* v_w    = (const float*)d_in[4];
    const float* w1     = (const float*)d_in[5];
    const float* b1     = (const float*)d_in[6];
    const float* w2     = (const float*)d_in[7];
    const float* b2     = (const float*)d_in[8];
    const float* ln_in_g  = (const float*)d_in[9];
    const float* ln_in_b  = (const float*)d_in[10];
    const float* ln_out_g = (const float*)d_in[11];
    const float* ln_out_b = (const float*)d_in[12];
    const float* ln_at_g  = (const float*)d_in[13];
    const float* ln_at_b  = (const float*)d_in[14];
    const float* ln_ml_g  = (const float*)d_in[15];
    const float* ln_ml_b  = (const float*)d_in[16];
    const float* tau    = (const float*)d_in[17];
    const float* rpb    = (const float*)d_in[18];
    float* out = (float*)d_out;

    float *pxn, *pk, *pv, *pxout, *plnq, *pq, *ph, *ph2, *pai, *pwt;
    cudaGetSymbolAddress((void**)&pxn,  g_xn);
    cudaGetSymbolAddress((void**)&pk,   g_k);
    cudaGetSymbolAddress((void**)&pv,   g_v);
    cudaGetSymbolAddress((void**)&pxout,g_xout);
    cudaGetSymbolAddress((void**)&plnq, g_lnq);
    cudaGetSymbolAddress((void**)&pq,   g_q);
    cudaGetSymbolAddress((void**)&ph,   g_h);
    cudaGetSymbolAddress((void**)&ph2,  g_h2);
    cudaGetSymbolAddress((void**)&pai,  g_ai);
    cudaGetSymbolAddress((void**)&pwt,  g_wt);

    // xn = LN(x); k/v projections
    ln_kernel<DIN, false><<<RTOT, DIN>>>(x, ln_in_g, ln_in_b, pxn);
    gemm_mma<0><<<dim3(2, RTOT / 128), 256>>>(pxn, k_w, nullptr, pk, RTOT, DIN, DIN);
    gemm_mma<0><<<dim3(3, RTOT / 128), 256>>>(pxn, v_w, nullptr, pv, RTOT, DOUT, DIN);

    // conv seed via im2col GEMM, then LN -> x_out
    wt_reorder_kernel<<<(DOUT * KCONV + 255) / 256, 256>>>(conv_w);
    im2col_kernel<<<(ROUT * KCONV + 255) / 256, 256>>>(x);
    gemm_mma<0><<<dim3(3, ROUT / 128), 256>>>(pai, pwt, nullptr, ph2, ROUT, DOUT, KCONV);
    ln_kernel<DOUT, false><<<ROUT, DOUT>>>(ph2, ln_out_g, ln_out_b, pxout);

    for (int it = 0; it < 3; ++it) {
        ln_kernel<DOUT, false><<<ROUT, DOUT>>>(pxout, ln_out_g, ln_out_b, plnq);
        gemm_mma<0><<<dim3(2, ROUT / 128), 256>>>(plnq, q_w, nullptr, pq, ROUT, DIN, DOUT);
        attn_kernel<<<RTOT / 8, 256>>>(rpb, tau);
        updates_kernel<<<ROUT, DOUT>>>(ln_at_g, ln_at_b);
        gemm_mma<2><<<dim3(6, ROUT / 128), 256>>>(pxout, w1, b1, ph, ROUT, HID, DOUT);
        gemm_mma<1><<<dim3(3, ROUT / 128), 256>>>(ph, w2, b2, ph2, ROUT, DOUT, HID);
        ln_kernel<DOUT, true><<<ROUT, DOUT>>>(ph2, ln_ml_g, ln_ml_b, pxout);
    }

    // outputs: dense a_ups/a_down rows (single pass), x_out copy
    writeA_kernel<<<RTOT, 256>>>(out + OFF_AUPS, out + OFF_ADOWN);
    copy_xout_kernel<<<(ROUT * DOUT + 255) / 256, 256>>>(out + OFF_X);
}